// round 3
// baseline (speedup 1.0000x reference)
#include <cuda_runtime.h>
#include <cuda_fp16.h>

// Problem constants (fixed shapes for this problem instance)
#define NCH      256
#define NB       2
#define NBOX     512
#define K_ROIS   1024   // NB * NBOX
#define NSAMP    14     // OUT * SR
#define OUT_PER_ROI 12544  // 256*49
// channels-last fp16 scratch: 27,200,000 halves = 54.4 MB (fits in L2)
__device__ __half g_cl[27200000];

// ---------------------------------------------------------------------------
// Pass A: ALL levels in one kernel. Transpose [B,C,P] -> [B,P,C] (fp32->fp16).
// Block = 32 pixels x 32 channels tile. 1D grid, level decoded from blockIdx.
// Level block counts: L0 1250*16=20000, L1 313*16=5008, L2 79*16=1264, L3 20*16=320
// ---------------------------------------------------------------------------
__global__ __launch_bounds__(256) void transpose_all(const float* __restrict__ f0,
                                                     const float* __restrict__ f1,
                                                     const float* __restrict__ f2,
                                                     const float* __restrict__ f3)
{
    __shared__ float tile[32][33];

    int id = blockIdx.x;
    int lvl, rel;
    if      (id < 20000) { lvl = 0; rel = id;         }
    else if (id < 25008) { lvl = 1; rel = id - 20000; }
    else if (id < 26272) { lvl = 2; rel = id - 25008; }
    else                 { lvl = 3; rel = id - 26272; }

    const int   P_[4]   = {40000, 10000, 2500, 625};
    const int   PT_[4]  = {1250, 313, 79, 20};
    const int   OFF_[4] = {0, 20480000, 25600000, 26880000};
    const float* srcs[4] = {f0, f1, f2, f3};

    const int P  = P_[lvl];
    const int pt = PT_[lvl];
    const int p0  = (rel % pt) * 32;
    const int rem = rel / pt;
    const int c0  = (rem & 7) * 32;
    const int b   = rem >> 3;

    const int tx = threadIdx.x & 31;
    const int ty = threadIdx.x >> 5;   // 0..7

    const float* src = srcs[lvl] + (size_t)b * NCH * P;
    #pragma unroll
    for (int i = 0; i < 4; ++i) {
        int c = c0 + ty + i * 8;
        int p = p0 + tx;
        if (p < P)
            tile[ty + i * 8][tx] = src[(size_t)c * P + p];
    }
    __syncthreads();

    // write: 32 pixels x 16 half2 = 512 half2, 256 threads x 2
    __half2* dst = (__half2*)(g_cl + OFF_[lvl] + (size_t)b * P * NCH);
    const int tid = threadIdx.x;
    #pragma unroll
    for (int i = 0; i < 2; ++i) {
        int idx = tid + i * 256;
        int p   = idx >> 4;        // 0..31
        int c2  = idx & 15;        // half2 index within 32 channels
        int pg  = p0 + p;
        if (pg < P) {
            float lo = tile[c2 * 2][p];
            float hi = tile[c2 * 2 + 1][p];
            dst[((size_t)pg * NCH + c0) / 2 + c2] = __floats2half2_rn(lo, hi);
        }
    }
}

// ---------------------------------------------------------------------------
// Pass B: one block per ROI. 256 threads:
//   tid & 31  -> channel group (8 consecutive channels, one uint4 of halves)
//   tid >> 5  -> bin group (8 groups over 49 bins)
// ---------------------------------------------------------------------------
#define SMEM_FLOATS 13608
#define SMEM_BYTES  (SMEM_FLOATS * 4)

__global__ __launch_bounds__(256) void roi_kernel(const float* __restrict__ boxes,
                                                  float* __restrict__ out)
{
    extern __shared__ float smem[];
    float*  stage = smem;                          // 12544 (output tile [c][49])
    float4* wsm   = (float4*)(smem + 12544);       // 196 float4
    int*    offsm = (int*)(smem + 12544 + 784);    // 196
    int*    ylsm  = offsm + 196;                   // 14
    int*    xlsm  = ylsm + 14;                     // 14
    float*  lysm  = (float*)(xlsm + 14);           // 14
    float*  lxsm  = lysm + 14;                     // 14
    float*  vysm  = lxsm + 14;                     // 14
    float*  vxsm  = vysm + 14;                     // 14

    const int k   = blockIdx.x;
    const int tid = threadIdx.x;
    const int b   = k >> 9;   // k / NBOX

    const float x1 = boxes[k * 4 + 0];
    const float y1 = boxes[k * 4 + 1];
    const float x2 = boxes[k * 4 + 2];
    const float y2 = boxes[k * 4 + 3];

    const float area = (x2 - x1) * (y2 - y1);
    const float sbox = sqrtf(fmaxf(area, 0.0f));
    const float lf   = floorf(4.0f + log2f(sbox / 224.0f) + 1e-6f);
    const int   lvl  = (int)fminf(fmaxf(lf, 2.0f), 5.0f) - 2;

    const int   HS[4]  = {200, 100, 50, 25};
    const float SCL[4] = {0.25f, 0.125f, 0.0625f, 0.03125f};
    const int   OFF[4] = {0, 20480000, 25600000, 26880000};

    const int   H  = HS[lvl];
    const int   W  = H;
    const float sc = SCL[lvl];

    const float bx1 = x1 * sc, by1 = y1 * sc;
    const float bx2 = x2 * sc, by2 = y2 * sc;
    const float rw  = fmaxf(bx2 - bx1, 1.0f);
    const float rh  = fmaxf(by2 - by1, 1.0f);
    const float bw  = rw * (1.0f / 7.0f);
    const float bh  = rh * (1.0f / 7.0f);

    // --- phase 1: separable y / x sample precompute ---
    if (tid < 14) {
        const int iy = tid;
        const float y = by1 + (float)(iy >> 1) * bh + ((float)(iy & 1) + 0.5f) * bh * 0.5f;
        const float v = (y >= -1.0f && y <= (float)H) ? 1.0f : 0.0f;
        const float yc = fminf(fmaxf(y, 0.0f), (float)(H - 1));
        int yl = (int)floorf(yc);
        if (yl > H - 2) yl = H - 2;
        ylsm[iy] = yl;
        lysm[iy] = yc - (float)yl;
        vysm[iy] = v;
    } else if (tid >= 32 && tid < 46) {
        const int ix = tid - 32;
        const float x = bx1 + (float)(ix >> 1) * bw + ((float)(ix & 1) + 0.5f) * bw * 0.5f;
        const float v = (x >= -1.0f && x <= (float)W) ? 1.0f : 0.0f;
        const float xc = fminf(fmaxf(x, 0.0f), (float)(W - 1));
        int xl = (int)floorf(xc);
        if (xl > W - 2) xl = W - 2;
        xlsm[ix] = xl;
        lxsm[ix] = xc - (float)xl;
        vxsm[ix] = v;
    }
    __syncthreads();

    // --- phase 2: per-sample combined offset + 4 bilinear weights ---
    for (int ss = tid; ss < NSAMP * NSAMP; ss += 256) {
        const int iy = ss / NSAMP;
        const int ix = ss - iy * NSAMP;
        const float ly = lysm[iy], lx = lxsm[ix];
        const float v  = vysm[iy] * vxsm[ix];
        const float hy = 1.0f - ly, hx = 1.0f - lx;
        wsm[ss]   = make_float4(hy * hx * v, hy * lx * v, ly * hx * v, ly * lx * v);
        offsm[ss] = (ylsm[iy] * W + xlsm[ix]) * NCH;   // in halves (elements)
    }
    __syncthreads();

    // --- phase 3: 49 bins over 8 bin-groups; 8 channels per thread (fp16 taps) ---
    const int cg = tid & 31;
    const int bg = tid >> 5;
    const __half* fb = g_cl + OFF[lvl] + (size_t)b * H * W * NCH + cg * 8;
    const int rs = W * NCH;   // +1 feature row, in halves

    for (int bin = bg; bin < 49; bin += 8) {
        const int ph = bin / 7;
        const int pw = bin - ph * 7;
        float a0 = 0.f, a1 = 0.f, a2 = 0.f, a3 = 0.f;
        float a4 = 0.f, a5 = 0.f, a6 = 0.f, a7 = 0.f;
        #pragma unroll
        for (int sub = 0; sub < 4; ++sub) {
            const int sI = (ph * 2 + (sub >> 1)) * NSAMP + (pw * 2 + (sub & 1));
            const float4 w = wsm[sI];
            const int    o = offsm[sI];
            const uint4 r00 = *(const uint4*)(fb + o);
            const uint4 r01 = *(const uint4*)(fb + o + NCH);
            const uint4 r10 = *(const uint4*)(fb + o + rs);
            const uint4 r11 = *(const uint4*)(fb + o + rs + NCH);
            #pragma unroll
            for (int j = 0; j < 4; ++j) {
                const float2 v00 = __half22float2(((const __half2*)&r00)[j]);
                const float2 v01 = __half22float2(((const __half2*)&r01)[j]);
                const float2 v10 = __half22float2(((const __half2*)&r10)[j]);
                const float2 v11 = __half22float2(((const __half2*)&r11)[j]);
                float lo = w.x * v00.x + w.y * v01.x + w.z * v10.x + w.w * v11.x;
                float hi = w.x * v00.y + w.y * v01.y + w.z * v10.y + w.w * v11.y;
                switch (j) {
                    case 0: a0 += lo; a1 += hi; break;
                    case 1: a2 += lo; a3 += hi; break;
                    case 2: a4 += lo; a5 += hi; break;
                    case 3: a6 += lo; a7 += hi; break;
                }
            }
        }
        const int base = (cg * 8) * 49 + bin;
        stage[base          ] = a0 * 0.25f;
        stage[base +  49    ] = a1 * 0.25f;
        stage[base +  49 * 2] = a2 * 0.25f;
        stage[base +  49 * 3] = a3 * 0.25f;
        stage[base +  49 * 4] = a4 * 0.25f;
        stage[base +  49 * 5] = a5 * 0.25f;
        stage[base +  49 * 6] = a6 * 0.25f;
        stage[base +  49 * 7] = a7 * 0.25f;
    }
    __syncthreads();

    // --- phase 4: fully coalesced float4 writeback of the ROI tile ---
    float4* op = (float4*)(out + (size_t)k * OUT_PER_ROI);
    const float4* sp = (const float4*)stage;
    for (int v = tid; v < OUT_PER_ROI / 4; v += 256)
        op[v] = sp[v];
}

// ---------------------------------------------------------------------------
extern "C" void kernel_launch(void* const* d_in, const int* in_sizes, int n_in,
                              void* d_out, int out_size)
{
    (void)in_sizes; (void)n_in; (void)out_size;
    const float* boxes = (const float*)d_in[4];
    float* out = (float*)d_out;

    cudaFuncSetAttribute(roi_kernel,
                         cudaFuncAttributeMaxDynamicSharedMemorySize, SMEM_BYTES);

    transpose_all<<<26592, 256>>>((const float*)d_in[0], (const float*)d_in[1],
                                  (const float*)d_in[2], (const float*)d_in[3]);

    roi_kernel<<<K_ROIS, 256, SMEM_BYTES>>>(boxes, out);
}

// round 5
// speedup vs baseline: 1.9166x; 1.9166x over previous
#include <cuda_runtime.h>
#include <cuda_fp16.h>

#define NCH      256
#define NB       2
#define NBOX     512
#define K_ROIS   1024
#define NSAMP    14
#define OUT_PER_ROI 12544  // 256*49
// channels-last fp16 scratch: 27,200,000 halves = 54.4 MB (fits in L2)
__device__ __half g_cl[27200000];

// ---------------------------------------------------------------------------
// Pass A: fused transpose+downconvert [B,C,P]f32 -> [B,P,C]f16, all 4 levels.
// Tile = 32 pixels x 64 channels. smem is PIXEL-major fp16 (stride 66 halves).
// Level block counts (pt*4ctiles*2b): L0 10000, L1 2504, L2 632, L3 160 -> 13296.
// ---------------------------------------------------------------------------
__global__ __launch_bounds__(256) void transpose_all(const float* __restrict__ f0,
                                                     const float* __restrict__ f1,
                                                     const float* __restrict__ f2,
                                                     const float* __restrict__ f3)
{
    __shared__ __half tile[32 * 66];   // [pixel][channel], 2-half pad per row

    const int id = blockIdx.x;
    int lvl, rel;
    if      (id < 10000) { lvl = 0; rel = id;         }
    else if (id < 12504) { lvl = 1; rel = id - 10000; }
    else if (id < 13136) { lvl = 2; rel = id - 12504; }
    else                 { lvl = 3; rel = id - 13136; }

    // branchless per-level constants (no local-memory arrays!)
    const int P   = lvl == 0 ? 40000 : lvl == 1 ? 10000 : lvl == 2 ? 2500 : 625;
    const int pt  = lvl == 0 ? 1250  : lvl == 1 ? 313   : lvl == 2 ? 79   : 20;
    const int OFF = lvl == 0 ? 0 : lvl == 1 ? 20480000 : lvl == 2 ? 25600000 : 26880000;
    const float* __restrict__ src0 =
        lvl == 0 ? f0 : lvl == 1 ? f1 : lvl == 2 ? f2 : f3;

    const int ptile = rel % pt;
    const int rem   = rel / pt;
    const int c0    = (rem & 3) * 64;
    const int b     = rem >> 2;
    const int p0    = ptile * 32;

    const int tid = threadIdx.x;
    const int tx  = tid & 31;    // pixel within tile
    const int ty  = tid >> 5;    // 0..7

    // read phase: 64 channel-rows x 32 pixels, fully coalesced 128B per warp-row
    const float* src = src0 + (size_t)b * NCH * P;
    const int p  = p0 + tx;
    const int pc = p < P ? p : P - 1;     // clamped (always-safe address)
    #pragma unroll
    for (int i = 0; i < 8; ++i) {
        const int cl = ty + i * 8;           // 0..63
        float v = src[(size_t)(c0 + cl) * P + pc];
        tile[tx * 66 + cl] = __float2half_rn(v);
    }
    __syncthreads();

    // write phase: each warp writes 4 pixels; one pixel = 32 half2 = 128B contig
    __half2* dst2 = (__half2*)(g_cl + OFF + (size_t)b * P * NCH);
    const __half2* t2 = (const __half2*)tile;
    const int c02 = (c0 >> 1);               // half2 offset of channel tile
    #pragma unroll
    for (int j = 0; j < 4; ++j) {
        const int pl = ty * 4 + j;           // pixel 0..31
        const int pg = p0 + pl;
        if (pg < P)
            dst2[(size_t)pg * (NCH / 2) + c02 + tx] = t2[pl * 33 + tx];
    }
}

// ---------------------------------------------------------------------------
// Pass B: one block per ROI. 256 threads:
//   tid & 31  -> channel group (8 consecutive channels, one uint4 of halves)
//   tid >> 5  -> bin group (8 groups over 49 bins)
// ---------------------------------------------------------------------------
#define SMEM_FLOATS 13608
#define SMEM_BYTES  (SMEM_FLOATS * 4)

__global__ __launch_bounds__(256) void roi_kernel(const float* __restrict__ boxes,
                                                  float* __restrict__ out)
{
    extern __shared__ float smem[];
    float*  stage = smem;                          // 12544 (output tile [c][49])
    float4* wsm   = (float4*)(smem + 12544);       // 196 float4
    int*    offsm = (int*)(smem + 12544 + 784);    // 196
    int*    ylsm  = offsm + 196;                   // 14
    int*    xlsm  = ylsm + 14;                     // 14
    float*  lysm  = (float*)(xlsm + 14);           // 14
    float*  lxsm  = lysm + 14;                     // 14
    float*  vysm  = lxsm + 14;                     // 14
    float*  vxsm  = vysm + 14;                     // 14

    const int k   = blockIdx.x;
    const int tid = threadIdx.x;
    const int b   = k >> 9;

    const float x1 = boxes[k * 4 + 0];
    const float y1 = boxes[k * 4 + 1];
    const float x2 = boxes[k * 4 + 2];
    const float y2 = boxes[k * 4 + 3];

    const float area = (x2 - x1) * (y2 - y1);
    const float sbox = sqrtf(fmaxf(area, 0.0f));
    const float lf   = floorf(4.0f + log2f(sbox / 224.0f) + 1e-6f);
    const int   lvl  = (int)fminf(fmaxf(lf, 2.0f), 5.0f) - 2;

    // branchless per-level constants (no local-memory arrays)
    const int   H   = lvl == 0 ? 200 : lvl == 1 ? 100 : lvl == 2 ? 50 : 25;
    const float sc  = lvl == 0 ? 0.25f : lvl == 1 ? 0.125f : lvl == 2 ? 0.0625f : 0.03125f;
    const int   OFF = lvl == 0 ? 0 : lvl == 1 ? 20480000 : lvl == 2 ? 25600000 : 26880000;
    const int   W   = H;

    const float bx1 = x1 * sc, by1 = y1 * sc;
    const float bx2 = x2 * sc, by2 = y2 * sc;
    const float rw  = fmaxf(bx2 - bx1, 1.0f);
    const float rh  = fmaxf(by2 - by1, 1.0f);
    const float bw  = rw * (1.0f / 7.0f);
    const float bh  = rh * (1.0f / 7.0f);

    // --- phase 1: separable y / x sample precompute ---
    if (tid < 14) {
        const int iy = tid;
        const float y = by1 + (float)(iy >> 1) * bh + ((float)(iy & 1) + 0.5f) * bh * 0.5f;
        const float v = (y >= -1.0f && y <= (float)H) ? 1.0f : 0.0f;
        const float yc = fminf(fmaxf(y, 0.0f), (float)(H - 1));
        int yl = (int)floorf(yc);
        if (yl > H - 2) yl = H - 2;
        ylsm[iy] = yl;
        lysm[iy] = yc - (float)yl;
        vysm[iy] = v;
    } else if (tid >= 32 && tid < 46) {
        const int ix = tid - 32;
        const float x = bx1 + (float)(ix >> 1) * bw + ((float)(ix & 1) + 0.5f) * bw * 0.5f;
        const float v = (x >= -1.0f && x <= (float)W) ? 1.0f : 0.0f;
        const float xc = fminf(fmaxf(x, 0.0f), (float)(W - 1));
        int xl = (int)floorf(xc);
        if (xl > W - 2) xl = W - 2;
        xlsm[ix] = xl;
        lxsm[ix] = xc - (float)xl;
        vxsm[ix] = v;
    }
    __syncthreads();

    // --- phase 2: per-sample combined offset + 4 bilinear weights ---
    for (int ss = tid; ss < NSAMP * NSAMP; ss += 256) {
        const int iy = ss / NSAMP;
        const int ix = ss - iy * NSAMP;
        const float ly = lysm[iy], lx = lxsm[ix];
        const float v  = vysm[iy] * vxsm[ix];
        const float hy = 1.0f - ly, hx = 1.0f - lx;
        wsm[ss]   = make_float4(hy * hx * v, hy * lx * v, ly * hx * v, ly * lx * v);
        offsm[ss] = (ylsm[iy] * W + xlsm[ix]) * NCH;   // in halves (elements)
    }
    __syncthreads();

    // --- phase 3: 49 bins over 8 bin-groups; 8 channels per thread (fp16 taps) ---
    const int cg = tid & 31;
    const int bg = tid >> 5;
    const __half* fb = g_cl + OFF + (size_t)b * H * W * NCH + cg * 8;
    const int rs = W * NCH;   // +1 feature row, in halves

    for (int bin = bg; bin < 49; bin += 8) {
        const int ph = bin / 7;
        const int pw = bin - ph * 7;
        float a0 = 0.f, a1 = 0.f, a2 = 0.f, a3 = 0.f;
        float a4 = 0.f, a5 = 0.f, a6 = 0.f, a7 = 0.f;
        #pragma unroll
        for (int sub = 0; sub < 4; ++sub) {
            const int sI = (ph * 2 + (sub >> 1)) * NSAMP + (pw * 2 + (sub & 1));
            const float4 w = wsm[sI];
            const int    o = offsm[sI];
            const uint4 r00 = *(const uint4*)(fb + o);
            const uint4 r01 = *(const uint4*)(fb + o + NCH);
            const uint4 r10 = *(const uint4*)(fb + o + rs);
            const uint4 r11 = *(const uint4*)(fb + o + rs + NCH);
            #pragma unroll
            for (int j = 0; j < 4; ++j) {
                const float2 v00 = __half22float2(((const __half2*)&r00)[j]);
                const float2 v01 = __half22float2(((const __half2*)&r01)[j]);
                const float2 v10 = __half22float2(((const __half2*)&r10)[j]);
                const float2 v11 = __half22float2(((const __half2*)&r11)[j]);
                float lo = w.x * v00.x + w.y * v01.x + w.z * v10.x + w.w * v11.x;
                float hi = w.x * v00.y + w.y * v01.y + w.z * v10.y + w.w * v11.y;
                switch (j) {
                    case 0: a0 += lo; a1 += hi; break;
                    case 1: a2 += lo; a3 += hi; break;
                    case 2: a4 += lo; a5 += hi; break;
                    case 3: a6 += lo; a7 += hi; break;
                }
            }
        }
        const int base = (cg * 8) * 49 + bin;
        stage[base          ] = a0 * 0.25f;
        stage[base +  49    ] = a1 * 0.25f;
        stage[base +  49 * 2] = a2 * 0.25f;
        stage[base +  49 * 3] = a3 * 0.25f;
        stage[base +  49 * 4] = a4 * 0.25f;
        stage[base +  49 * 5] = a5 * 0.25f;
        stage[base +  49 * 6] = a6 * 0.25f;
        stage[base +  49 * 7] = a7 * 0.25f;
    }
    __syncthreads();

    // --- phase 4: fully coalesced float4 writeback of the ROI tile ---
    float4* op = (float4*)(out + (size_t)k * OUT_PER_ROI);
    const float4* sp = (const float4*)stage;
    for (int v = tid; v < OUT_PER_ROI / 4; v += 256)
        op[v] = sp[v];
}

// ---------------------------------------------------------------------------
extern "C" void kernel_launch(void* const* d_in, const int* in_sizes, int n_in,
                              void* d_out, int out_size)
{
    (void)in_sizes; (void)n_in; (void)out_size;
    const float* boxes = (const float*)d_in[4];
    float* out = (float*)d_out;

    cudaFuncSetAttribute(roi_kernel,
                         cudaFuncAttributeMaxDynamicSharedMemorySize, SMEM_BYTES);

    transpose_all<<<13296, 256>>>((const float*)d_in[0], (const float*)d_in[1],
                                  (const float*)d_in[2], (const float*)d_in[3]);

    roi_kernel<<<K_ROIS, 256, SMEM_BYTES>>>(boxes, out);
}